// round 3
// baseline (speedup 1.0000x reference)
#include <cuda_runtime.h>
#include <math.h>

// ---------------- problem constants ----------------
#define BATCH   2
#define SEQ     2048
#define DIM     1024
#define HEADS   16
#define DHEAD   64
#define LATENT  256
#define MROWS   (BATCH * SEQ)          // 4096
#define SCALE   0.125f                 // DHEAD^-0.5

// ---------------- scratch (device globals; no allocation APIs) ----------------
__device__ float g_q  [MROWS * DIM];     // 16 MB
__device__ float g_lat[MROWS * LATENT];  //  4 MB
__device__ float g_k  [MROWS * DIM];     // 16 MB
__device__ float g_v  [MROWS * DIM];     // 16 MB
__device__ float g_ao [MROWS * DIM];     // 16 MB

// packed fp32x2 FMA (Blackwell): d = a*b + d, elementwise on 2 floats
#define FMA2(acc, a, b) \
    asm("fma.rn.f32x2 %0, %1, %2, %0;" : "+l"(acc) : "l"(a), "l"(b))
#define UNPK(lo, hi, v) \
    asm("mov.b64 {%0, %1}, %2;" : "=f"(lo), "=f"(hi) : "l"(v))

// ============================================================================
// SGEMM + bias via fma.rn.f32x2:  C[M,N] = A[M,K] @ B[K,N] + bias[N]
// 128x128 tile, BK=8, double-buffered, 256 threads, 8x8 microtile
// (rows {4ty..4ty+3, 64+4ty..}, cols {4tx..4tx+3, 64+4tx..}).
// A tile stored DUPLICATED in smem so ulonglong2 LDS yields {a,a} pairs.
// Requires M,N multiples of 128; K multiple of 8.
// ============================================================================
__global__ __launch_bounds__(256, 2)
void gemm_bias_kernel(const float* __restrict__ A,
                      const float* __restrict__ B,
                      const float* __restrict__ bias,
                      float* __restrict__ C,
                      int M, int N, int K)
{
    __shared__ __align__(16) float sA2[2][8][260];  // [kk][2*row(+dup)], padded
    __shared__ __align__(16) float sB [2][8][128];

    const int t  = threadIdx.x;
    const int tx = t & 15;
    const int ty = t >> 4;
    const int m0 = blockIdx.y * 128;
    const int n0 = blockIdx.x * 128;

    // loader coords
    const int arow = t >> 1;          // 0..127
    const int acol = (t & 1) * 4;     // 0 or 4
    const int brow = t >> 5;          // 0..7
    const int bcol = (t & 31) * 4;    // 0..124

    const float* Aptr = A + (size_t)(m0 + arow) * K + acol;
    const float* Bptr = B + (size_t)brow * N + n0 + bcol;

    unsigned long long acc2[8][4];
#pragma unroll
    for (int j = 0; j < 8; j++)
#pragma unroll
        for (int i = 0; i < 4; i++) acc2[j][i] = 0ull;

    const int KT = K / 8;

    // prologue: tile 0 -> buffer 0
    {
        float4 fa = *reinterpret_cast<const float4*>(Aptr);
        float af[4] = {fa.x, fa.y, fa.z, fa.w};
#pragma unroll
        for (int c = 0; c < 4; c++) {
            sA2[0][acol + c][2 * arow]     = af[c];
            sA2[0][acol + c][2 * arow + 1] = af[c];
        }
        *reinterpret_cast<float4*>(&sB[0][brow][bcol]) =
            *reinterpret_cast<const float4*>(Bptr);
    }
    __syncthreads();

    int buf = 0;
    for (int kt = 0; kt < KT; kt++) {
        float4 fa, fb;
        const bool has_next = (kt + 1 < KT);
        if (has_next) {
            fa = *reinterpret_cast<const float4*>(Aptr + (size_t)(kt + 1) * 8);
            fb = *reinterpret_cast<const float4*>(Bptr + (size_t)(kt + 1) * 8 * N);
        }

#pragma unroll
        for (int kk = 0; kk < 8; kk++) {
            const ulonglong2* pa0 =
                reinterpret_cast<const ulonglong2*>(&sA2[buf][kk][8 * ty]);
            const ulonglong2* pa1 =
                reinterpret_cast<const ulonglong2*>(&sA2[buf][kk][128 + 8 * ty]);
            ulonglong2 a01 = pa0[0];
            ulonglong2 a23 = pa0[1];
            ulonglong2 a45 = pa1[0];
            ulonglong2 a67 = pa1[1];
            const ulonglong2* pb0 =
                reinterpret_cast<const ulonglong2*>(&sB[buf][kk][4 * tx]);
            const ulonglong2* pb1 =
                reinterpret_cast<const ulonglong2*>(&sB[buf][kk][64 + 4 * tx]);
            ulonglong2 bl0 = pb0[0];
            ulonglong2 bl1 = pb1[0];

            unsigned long long a2[8] = {a01.x, a01.y, a23.x, a23.y,
                                        a45.x, a45.y, a67.x, a67.y};
            unsigned long long b2[4] = {bl0.x, bl0.y, bl1.x, bl1.y};
#pragma unroll
            for (int j = 0; j < 8; j++)
#pragma unroll
                for (int i = 0; i < 4; i++)
                    FMA2(acc2[j][i], a2[j], b2[i]);
        }

        if (has_next) {
            const int nb = buf ^ 1;
            float af[4] = {fa.x, fa.y, fa.z, fa.w};
#pragma unroll
            for (int c = 0; c < 4; c++) {
                sA2[nb][acol + c][2 * arow]     = af[c];
                sA2[nb][acol + c][2 * arow + 1] = af[c];
            }
            *reinterpret_cast<float4*>(&sB[nb][brow][bcol]) = fb;
            __syncthreads();
            buf = nb;
        }
    }

    // epilogue: unpack + bias + float4 stores
    float4 bias0 = *reinterpret_cast<const float4*>(&bias[n0 + 4 * tx]);
    float4 bias1 = *reinterpret_cast<const float4*>(&bias[n0 + 64 + 4 * tx]);
#pragma unroll
    for (int j = 0; j < 8; j++) {
        const int r = m0 + ((j < 4) ? (4 * ty + j) : (64 + 4 * ty + (j - 4)));
        float x0, x1, x2, x3, y0, y1, y2, y3;
        UNPK(x0, x1, acc2[j][0]);
        UNPK(x2, x3, acc2[j][1]);
        UNPK(y0, y1, acc2[j][2]);
        UNPK(y2, y3, acc2[j][3]);
        float4 o0 = {x0 + bias0.x, x1 + bias0.y, x2 + bias0.z, x3 + bias0.w};
        float4 o1 = {y0 + bias1.x, y1 + bias1.y, y2 + bias1.z, y3 + bias1.w};
        float* crow = C + (size_t)r * N + n0;
        *reinterpret_cast<float4*>(&crow[4 * tx])      = o0;
        *reinterpret_cast<float4*>(&crow[64 + 4 * tx]) = o1;
    }
}

// ============================================================================
// Flash attention, fp32, per (batch, head). Q tile 128, K tile 64.
// 256 threads: rows r = ty+16j (j<8), cols/keys c = tx+16i (i<4).
// smem (dynamic 82944B):
//   sQ  [128][65] at 0      (Q pre-scaled by SCALE; pad-65 kills bank dup)
//   sKt [64][65]  at 33280  (K transposed dh-major; conflict-free kv reads)
//   sP  [128][65] aliases sKt region (K dead after S compute)
//   sV  [64][64]  at 66560
// ============================================================================
#define QTILE 128
#define KTILE 64
#define FLASH_SMEM_BYTES 82944

__global__ __launch_bounds__(256, 2)
void flash_attn_kernel(const float* __restrict__ q,
                       const float* __restrict__ k,
                       const float* __restrict__ v,
                       float* __restrict__ o)
{
    extern __shared__ __align__(16) char smem[];
    float* sQ  = reinterpret_cast<float*>(smem);            // [128][65]
    float* sKt = reinterpret_cast<float*>(smem + 33280);    // [64][65]
    float* sP  = sKt;                                       // [128][65] alias
    float* sV  = reinterpret_cast<float*>(smem + 66560);    // [64][64]

    const int t  = threadIdx.x;
    const int tx = t & 15;
    const int ty = t >> 4;
    const int b  = blockIdx.z;
    const int h  = blockIdx.y;
    const int q0 = blockIdx.x * QTILE;
    const size_t hoff = (size_t)h * DHEAD;

    // ---- load Q tile (128 x 64), pre-scaled ----
#pragma unroll
    for (int p = 0; p < 8; p++) {
        int u    = t + 256 * p;       // 0..2047
        int row  = u >> 4;            // 0..127
        int col4 = u & 15;
        float4 f = *reinterpret_cast<const float4*>(
            &q[((size_t)(b * SEQ + q0 + row)) * DIM + hoff + col4 * 4]);
        float* dst = &sQ[row * 65 + col4 * 4];
        dst[0] = f.x * SCALE;
        dst[1] = f.y * SCALE;
        dst[2] = f.z * SCALE;
        dst[3] = f.w * SCALE;
    }

    float m_i[8], l_i[8], oa[8][4];
#pragma unroll
    for (int j = 0; j < 8; j++) {
        m_i[j] = -INFINITY;
        l_i[j] = 0.0f;
#pragma unroll
        for (int i = 0; i < 4; i++) oa[j][i] = 0.0f;
    }

    for (int kt = 0; kt < SEQ / KTILE; kt++) {
        const int kb = kt * KTILE;
        __syncthreads();   // prev PV done before K/V overwrite sP/sV regions

        // ---- load K (transposed into sKt) and V tiles (64 x 64) ----
#pragma unroll
        for (int p = 0; p < 4; p++) {
            int u    = t + 256 * p;   // 0..1023
            int row  = u >> 4;        // 0..63
            int col4 = u & 15;
            size_t g = ((size_t)(b * SEQ + kb + row)) * DIM + hoff + col4 * 4;
            float4 fk = *reinterpret_cast<const float4*>(&k[g]);
            sKt[(col4 * 4 + 0) * 65 + row] = fk.x;
            sKt[(col4 * 4 + 1) * 65 + row] = fk.y;
            sKt[(col4 * 4 + 2) * 65 + row] = fk.z;
            sKt[(col4 * 4 + 3) * 65 + row] = fk.w;
            float4 fv = *reinterpret_cast<const float4*>(&v[g]);
            *reinterpret_cast<float4*>(&sV[row * 64 + col4 * 4]) = fv;
        }
        __syncthreads();

        // ---- S = Qs K^T (128 x 64), 8x4 per thread ----
        float s[8][4];
#pragma unroll
        for (int j = 0; j < 8; j++)
#pragma unroll
            for (int i = 0; i < 4; i++) s[j][i] = 0.0f;

#pragma unroll 8
        for (int kk = 0; kk < KTILE; kk++) {
            float qv[8], kv[4];
#pragma unroll
            for (int j = 0; j < 8; j++) qv[j] = sQ[(ty + 16 * j) * 65 + kk];
#pragma unroll
            for (int i = 0; i < 4; i++) kv[i] = sKt[kk * 65 + tx + 16 * i];
#pragma unroll
            for (int j = 0; j < 8; j++)
#pragma unroll
                for (int i = 0; i < 4; i++)
                    s[j][i] = fmaf(qv[j], kv[i], s[j][i]);
        }

        // ---- online softmax (row reductions across 16 tx lanes) ----
#pragma unroll
        for (int j = 0; j < 8; j++) {
            float mx = fmaxf(fmaxf(s[j][0], s[j][1]), fmaxf(s[j][2], s[j][3]));
#pragma unroll
            for (int off = 8; off > 0; off >>= 1)
                mx = fmaxf(mx, __shfl_xor_sync(0xffffffffu, mx, off, 16));
            float mn = fmaxf(m_i[j], mx);
            float al = __expf(m_i[j] - mn);
            float rs = 0.0f;
#pragma unroll
            for (int i = 0; i < 4; i++) {
                s[j][i] = __expf(s[j][i] - mn);
                rs += s[j][i];
            }
#pragma unroll
            for (int off = 8; off > 0; off >>= 1)
                rs += __shfl_xor_sync(0xffffffffu, rs, off, 16);
            l_i[j] = l_i[j] * al + rs;
            m_i[j] = mn;
#pragma unroll
            for (int i = 0; i < 4; i++) oa[j][i] *= al;
        }
        __syncthreads();   // all S reads of sKt done before P overwrites it

        // ---- write P ----
#pragma unroll
        for (int j = 0; j < 8; j++)
#pragma unroll
            for (int i = 0; i < 4; i++)
                sP[(ty + 16 * j) * 65 + tx + 16 * i] = s[j][i];
        __syncthreads();

        // ---- O += P @ V ----
#pragma unroll 8
        for (int jj = 0; jj < KTILE; jj++) {
            float pv[8], vv[4];
#pragma unroll
            for (int j = 0; j < 8; j++) pv[j] = sP[(ty + 16 * j) * 65 + jj];
#pragma unroll
            for (int i = 0; i < 4; i++) vv[i] = sV[jj * 64 + tx + 16 * i];
#pragma unroll
            for (int j = 0; j < 8; j++)
#pragma unroll
                for (int i = 0; i < 4; i++)
                    oa[j][i] = fmaf(pv[j], vv[i], oa[j][i]);
        }
    }

    // ---- normalize + write ----
#pragma unroll
    for (int j = 0; j < 8; j++) {
        float inv = 1.0f / l_i[j];
        const size_t row = (size_t)(b * SEQ + q0 + ty + 16 * j);
#pragma unroll
        for (int i = 0; i < 4; i++)
            o[row * DIM + hoff + tx + 16 * i] = oa[j][i] * inv;
    }
}

// ============================================================================
// launch
// ============================================================================
extern "C" void kernel_launch(void* const* d_in, const int* in_sizes, int n_in,
                              void* d_out, int out_size)
{
    const float* x  = (const float*)d_in[0];
    const float* Wq = (const float*)d_in[1];
    const float* bq = (const float*)d_in[2];
    const float* Wl = (const float*)d_in[3];
    const float* bl = (const float*)d_in[4];
    const float* Wk = (const float*)d_in[5];
    const float* bk = (const float*)d_in[6];
    const float* Wv = (const float*)d_in[7];
    const float* bv = (const float*)d_in[8];
    const float* Wo = (const float*)d_in[9];
    const float* bo = (const float*)d_in[10];
    float* out = (float*)d_out;

    float *pq, *plat, *pk, *pv, *pao;
    cudaGetSymbolAddress((void**)&pq,   g_q);
    cudaGetSymbolAddress((void**)&plat, g_lat);
    cudaGetSymbolAddress((void**)&pk,   g_k);
    cudaGetSymbolAddress((void**)&pv,   g_v);
    cudaGetSymbolAddress((void**)&pao,  g_ao);

    cudaFuncSetAttribute(flash_attn_kernel,
                         cudaFuncAttributeMaxDynamicSharedMemorySize,
                         FLASH_SMEM_BYTES);

    dim3 thr(256);

    // q = x @ Wq + bq            [4096,1024] = [4096,1024]@[1024,1024]
    gemm_bias_kernel<<<dim3(DIM / 128, MROWS / 128), thr>>>(x, Wq, bq, pq, MROWS, DIM, DIM);
    // latent = x @ Wl + bl       [4096,256]  = [4096,1024]@[1024,256]
    gemm_bias_kernel<<<dim3(LATENT / 128, MROWS / 128), thr>>>(x, Wl, bl, plat, MROWS, LATENT, DIM);
    // k = latent @ Wk + bk       [4096,1024] = [4096,256]@[256,1024]
    gemm_bias_kernel<<<dim3(DIM / 128, MROWS / 128), thr>>>(plat, Wk, bk, pk, MROWS, DIM, LATENT);
    // v = latent @ Wv + bv
    gemm_bias_kernel<<<dim3(DIM / 128, MROWS / 128), thr>>>(plat, Wv, bv, pv, MROWS, DIM, LATENT);

    // attention -> g_ao  [B,S,D]
    flash_attn_kernel<<<dim3(SEQ / QTILE, HEADS, BATCH), thr, FLASH_SMEM_BYTES>>>(pq, pk, pv, pao);

    // out = ao @ Wo + bo
    gemm_bias_kernel<<<dim3(DIM / 128, MROWS / 128), thr>>>(pao, Wo, bo, out, MROWS, DIM, DIM);
}